// round 2
// baseline (speedup 1.0000x reference)
#include <cuda_runtime.h>
#include <cuda_bf16.h>
#include <cstdint>

#define N_SRC 4096
#define D     256
#define TOT   8192
#define TILE  128
#define NT    (TOT / TILE)     // 64 tiles per dim
#define HALF_NT (NT / 2)       // 32: tiles below this index are "source"
#define LDS_PAD 264            // padded row stride (bf16 elems): 528B -> conflict-free ldmatrix

// -------- device scratch (no allocations allowed) --------
__device__ __nv_bfloat16 g_bf[(size_t)TOT * D];
__device__ float  g_sq[TOT];
__device__ double g_acc;

// ---------------------------------------------------------------------------
// Kernel 1: convert fp32 -> bf16, compute sq[i] = sum(bf16(x)^2) per row,
// zero the global accumulator. One block (256 threads) per row.
// ---------------------------------------------------------------------------
__global__ void prep_kernel(const float* __restrict__ src,
                            const float* __restrict__ tgt) {
    int row = blockIdx.x;
    int tid = threadIdx.x;
    const float* base = (row < N_SRC) ? (src + (size_t)row * D)
                                      : (tgt + (size_t)(row - N_SRC) * D);
    float v = base[tid];
    __nv_bfloat16 b = __float2bfloat16(v);
    g_bf[(size_t)row * D + tid] = b;
    float vb = __bfloat162float(b);
    float s = vb * vb;

    // block reduce (256 threads)
    #pragma unroll
    for (int o = 16; o; o >>= 1) s += __shfl_xor_sync(0xFFFFFFFFu, s, o);
    __shared__ float wsum[8];
    if ((tid & 31) == 0) wsum[tid >> 5] = s;
    __syncthreads();
    if (tid < 8) {
        float x = wsum[tid];
        #pragma unroll
        for (int o = 4; o; o >>= 1) x += __shfl_xor_sync(0xFFu, x, o, 8);
        if (tid == 0) g_sq[row] = x;
    }
    if (row == 0 && tid == 0) g_acc = 0.0;
}

// ---------------------------------------------------------------------------
// mma.sync helpers
// ---------------------------------------------------------------------------
__device__ __forceinline__ void ldsm_x4(uint32_t& r0, uint32_t& r1,
                                        uint32_t& r2, uint32_t& r3,
                                        uint32_t addr) {
    asm volatile(
        "ldmatrix.sync.aligned.m8n8.x4.shared.b16 {%0,%1,%2,%3}, [%4];"
        : "=r"(r0), "=r"(r1), "=r"(r2), "=r"(r3)
        : "r"(addr));
}

__device__ __forceinline__ void mma_bf16(float* c, const uint32_t* a,
                                         uint32_t b0, uint32_t b1) {
    asm volatile(
        "mma.sync.aligned.m16n8k16.row.col.f32.bf16.bf16.f32 "
        "{%0,%1,%2,%3}, {%4,%5,%6,%7}, {%8,%9}, {%0,%1,%2,%3};"
        : "+f"(c[0]), "+f"(c[1]), "+f"(c[2]), "+f"(c[3])
        : "r"(a[0]), "r"(a[1]), "r"(a[2]), "r"(a[3]), "r"(b0), "r"(b1));
}

// ---------------------------------------------------------------------------
// Kernel 2: one CTA per 128x128 tile of the 8192x8192 kernel matrix
// (upper block triangle only). 256 threads = 8 warps, each warp 32x64.
// Gram via bf16 mma.sync, fused exp-sum epilogue, signed accumulate.
// ---------------------------------------------------------------------------
__global__ void __launch_bounds__(256, 1)
mmd_kernel() {
    const int bi = blockIdx.x;   // row tile
    const int bj = blockIdx.y;   // col tile
    if (bj < bi) return;         // symmetry: upper triangle only

    extern __shared__ char smem_raw[];
    __nv_bfloat16* As = (__nv_bfloat16*)smem_raw;                 // [128][LDS_PAD]
    __nv_bfloat16* Bs = As + TILE * LDS_PAD;                      // [128][LDS_PAD]
    float* sqA = (float*)(Bs + TILE * LDS_PAD);                   // [128]
    float* sqB = sqA + TILE;                                      // [128]

    const int tid  = threadIdx.x;
    const int lane = tid & 31;
    const int warp = tid >> 5;
    const int wm   = warp & 3;   // 4 row-warps * 32 rows
    const int wn   = warp >> 2;  // 2 col-warps * 64 cols

    // ---- load tiles (128x256 bf16 each) with 16B vectors ----
    {
        const __nv_bfloat16* Ag = g_bf + (size_t)bi * TILE * D;
        const __nv_bfloat16* Bg = g_bf + (size_t)bj * TILE * D;
        #pragma unroll
        for (int it = 0; it < 16; it++) {            // 4096 uint4 / 256 threads
            int idx = it * 256 + tid;
            int r = idx >> 5;                        // 32 uint4 per row
            int c = idx & 31;
            uint4 va = ((const uint4*)(Ag + (size_t)r * D))[c];
            *(uint4*)(&As[r * LDS_PAD + c * 8]) = va;
            uint4 vb = ((const uint4*)(Bg + (size_t)r * D))[c];
            *(uint4*)(&Bs[r * LDS_PAD + c * 8]) = vb;
        }
        if (tid < TILE)        sqA[tid] = g_sq[bi * TILE + tid];
        else if (tid < 2*TILE) sqB[tid - TILE] = g_sq[bj * TILE + (tid - TILE)];
    }
    __syncthreads();

    // ---- ldmatrix base addresses ----
    uint32_t as_base = (uint32_t)__cvta_generic_to_shared(As);
    uint32_t bs_base = (uint32_t)__cvta_generic_to_shared(Bs);

    // A x4: threads 0-15 -> rows (lane&15) col 0; threads 16-31 -> rows (lane&15) col 8
    uint32_t addrA[2];
    #pragma unroll
    for (int mt = 0; mt < 2; mt++) {
        int r = wm * 32 + mt * 16 + (lane & 15);
        int coff = (lane >> 4) * 8;
        addrA[mt] = as_base + (uint32_t)(r * LDS_PAD + coff) * 2;
    }
    // B x4 covers two n8 tiles: quads 0..3 -> (n0-7,k0-7),(n0-7,k8-15),(n8-15,k0-7),(n8-15,k8-15)
    uint32_t addrB[4];
    #pragma unroll
    for (int nt4 = 0; nt4 < 4; nt4++) {
        int quad = lane >> 3;
        int r = wn * 64 + nt4 * 16 + (lane & 7) + ((quad & 2) ? 8 : 0);
        int coff = (quad & 1) * 8;
        addrB[nt4] = bs_base + (uint32_t)(r * LDS_PAD + coff) * 2;
    }

    float c[2][8][4];
    #pragma unroll
    for (int mt = 0; mt < 2; mt++)
        #pragma unroll
        for (int nt = 0; nt < 8; nt++)
            #pragma unroll
            for (int e = 0; e < 4; e++) c[mt][nt][e] = 0.f;

    // ---- main loop: K = 256 in 16 steps of k16 ----
    #pragma unroll
    for (int kk = 0; kk < 16; kk++) {
        uint32_t kb = (uint32_t)kk * 32;  // 16 bf16 = 32 bytes
        uint32_t a[2][4];
        ldsm_x4(a[0][0], a[0][1], a[0][2], a[0][3], addrA[0] + kb);
        ldsm_x4(a[1][0], a[1][1], a[1][2], a[1][3], addrA[1] + kb);
        uint32_t b[4][4];
        #pragma unroll
        for (int nt4 = 0; nt4 < 4; nt4++)
            ldsm_x4(b[nt4][0], b[nt4][1], b[nt4][2], b[nt4][3], addrB[nt4] + kb);

        #pragma unroll
        for (int mt = 0; mt < 2; mt++)
            #pragma unroll
            for (int nt4 = 0; nt4 < 4; nt4++) {
                mma_bf16(c[mt][2 * nt4],     a[mt], b[nt4][0], b[nt4][1]);
                mma_bf16(c[mt][2 * nt4 + 1], a[mt], b[nt4][2], b[nt4][3]);
            }
    }

    // ---- epilogue: l2 -> sum of 5 gaussian kernels -> signed accumulate ----
    const float NEG_L2E_16 = -1.4426950408889634f / 16.0f;  // -log2(e)/16
    const int g = lane >> 2;
    const int q = lane & 3;
    float wgt = (((bi < HALF_NT) == (bj < HALF_NT)) ? 1.0f : -1.0f)
              * ((bi == bj) ? 1.0f : 2.0f);

    float acc = 0.f;
    #pragma unroll
    for (int mt = 0; mt < 2; mt++) {
        #pragma unroll
        for (int nt = 0; nt < 8; nt++) {
            #pragma unroll
            for (int e = 0; e < 4; e++) {
                int r    = wm * 32 + mt * 16 + g + ((e >> 1) << 3);
                int cidx = wn * 64 + nt * 8 + q * 2 + (e & 1);
                float l2 = sqA[r] + sqB[cidx] - 2.0f * c[mt][nt][e];
                float u  = exp2f(l2 * NEG_L2E_16);   // exp(-l2/16)
                float u2 = u * u, u4 = u2 * u2, u8 = u4 * u4, u16 = u8 * u8;
                acc += ((u + u2) + (u4 + u8)) + u16;
            }
        }
    }
    // warp reduce + one double atomic per warp
    #pragma unroll
    for (int o = 16; o; o >>= 1) acc += __shfl_xor_sync(0xFFFFFFFFu, acc, o);
    if (lane == 0) atomicAdd(&g_acc, (double)(acc * wgt));
}

// ---------------------------------------------------------------------------
// Kernel 3: finalize scalar
// ---------------------------------------------------------------------------
__global__ void fin_kernel(float* out) {
    out[0] = (float)(g_acc * (1.0 / ((double)N_SRC * (double)N_SRC)));
}

extern "C" void kernel_launch(void* const* d_in, const int* in_sizes, int n_in,
                              void* d_out, int out_size) {
    const float* src = (const float*)d_in[0];
    const float* tgt = (const float*)d_in[1];
    float* out = (float*)d_out;

    const int SMEM = 2 * TILE * LDS_PAD * 2 + 2 * TILE * (int)sizeof(float);
    cudaFuncSetAttribute(mmd_kernel, cudaFuncAttributeMaxDynamicSharedMemorySize, SMEM);

    prep_kernel<<<TOT, 256>>>(src, tgt);
    dim3 grid(NT, NT);
    mmd_kernel<<<grid, 256, SMEM>>>();
    fin_kernel<<<1, 1>>>(out);
}

// round 5
// speedup vs baseline: 1.3154x; 1.3154x over previous
#include <cuda_runtime.h>
#include <cuda_bf16.h>
#include <cstdint>

#define N_SRC 4096
#define D     256
#define TOT   8192
#define TILE  128
#define NT    (TOT / TILE)     // 64
#define HALF_NT (NT / 2)       // 32
#define CK    64               // K-chunk (bf16 elems)
#define NC    (D / CK)         // 4 chunks
#define ROWB  144              // bytes per smem row (72 bf16): conflict-free ldmatrix
#define MATB  (TILE * ROWB)    // 18432 bytes per matrix per stage
#define STAGEB (2 * MATB)      // 36864 bytes per stage (A+B)
#define SQ_OFF (2 * STAGEB)    // 73728
#define SMEM_TOTAL (SQ_OFF + 2 * TILE * 4)   // 74752

// -------- device scratch --------
__device__ __nv_bfloat16 g_bf[(size_t)TOT * D];
__device__ float  g_sq[TOT];
__device__ double g_acc;

// ---------------------------------------------------------------------------
// Kernel 1: fp32 -> bf16 + per-row sumsq of the rounded values. Warp per row.
// ---------------------------------------------------------------------------
__global__ void prep_kernel(const float* __restrict__ src,
                            const float* __restrict__ tgt) {
    int lane = threadIdx.x & 31;
    int warp = threadIdx.x >> 5;
    int row  = blockIdx.x * 8 + warp;
    const float* base = (row < N_SRC) ? (src + (size_t)row * D)
                                      : (tgt + (size_t)(row - N_SRC) * D);
    float4 v0 = ((const float4*)base)[lane * 2];
    float4 v1 = ((const float4*)base)[lane * 2 + 1];

    __nv_bfloat162 b01 = __floats2bfloat162_rn(v0.x, v0.y);
    __nv_bfloat162 b23 = __floats2bfloat162_rn(v0.z, v0.w);
    __nv_bfloat162 b45 = __floats2bfloat162_rn(v1.x, v1.y);
    __nv_bfloat162 b67 = __floats2bfloat162_rn(v1.z, v1.w);

    uint4 o;
    o.x = *(uint32_t*)&b01; o.y = *(uint32_t*)&b23;
    o.z = *(uint32_t*)&b45; o.w = *(uint32_t*)&b67;
    ((uint4*)(g_bf + (size_t)row * D))[lane] = o;

    float f0 = __low2float(b01), f1 = __high2float(b01);
    float f2 = __low2float(b23), f3 = __high2float(b23);
    float f4 = __low2float(b45), f5 = __high2float(b45);
    float f6 = __low2float(b67), f7 = __high2float(b67);
    float s = f0*f0 + f1*f1 + f2*f2 + f3*f3 + f4*f4 + f5*f5 + f6*f6 + f7*f7;
    #pragma unroll
    for (int o2 = 16; o2; o2 >>= 1) s += __shfl_xor_sync(0xFFFFFFFFu, s, o2);
    if (lane == 0) g_sq[row] = s;
    if (row == 0 && lane == 0) g_acc = 0.0;
}

// ---------------------------------------------------------------------------
// mma helpers
// ---------------------------------------------------------------------------
__device__ __forceinline__ void ldsm_x4(uint32_t& r0, uint32_t& r1,
                                        uint32_t& r2, uint32_t& r3,
                                        uint32_t addr) {
    asm volatile(
        "ldmatrix.sync.aligned.m8n8.x4.shared.b16 {%0,%1,%2,%3}, [%4];"
        : "=r"(r0), "=r"(r1), "=r"(r2), "=r"(r3)
        : "r"(addr));
}

__device__ __forceinline__ void mma_bf16(float* c, const uint32_t* a,
                                         uint32_t b0, uint32_t b1) {
    asm volatile(
        "mma.sync.aligned.m16n8k16.row.col.f32.bf16.bf16.f32 "
        "{%0,%1,%2,%3}, {%4,%5,%6,%7}, {%8,%9}, {%0,%1,%2,%3};"
        : "+f"(c[0]), "+f"(c[1]), "+f"(c[2]), "+f"(c[3])
        : "r"(a[0]), "r"(a[1]), "r"(a[2]), "r"(a[3]), "r"(b0), "r"(b1));
}

__device__ __forceinline__ void cp16(uint32_t dst, const void* src) {
    asm volatile("cp.async.cg.shared.global [%0], [%1], 16;"
                 :: "r"(dst), "l"(src) : "memory");
}

__device__ __forceinline__ float ex2f(float x) {
    float y;
    asm("ex2.approx.ftz.f32 %0, %1;" : "=f"(y) : "f"(x));
    return y;
}

// ---------------------------------------------------------------------------
// Kernel 2: one CTA per 128x128 tile (upper block triangle), 8 warps (32x64
// warp tiles). cp.async 2-stage K-chunk pipeline; 2 CTAs/SM.
// ---------------------------------------------------------------------------
__global__ void __launch_bounds__(256, 2)
mmd_kernel() {
    const int bi = blockIdx.x;
    const int bj = blockIdx.y;
    if (bj < bi) return;

    extern __shared__ __align__(128) char smem[];
    uint32_t sb = (uint32_t)__cvta_generic_to_shared(smem);

    const int tid  = threadIdx.x;
    const int lane = tid & 31;
    const int warp = tid >> 5;
    const int wm   = warp & 3;
    const int wn   = warp >> 2;

    float* sqA = (float*)(smem + SQ_OFF);
    float* sqB = sqA + TILE;
    if (tid < TILE)        sqA[tid] = g_sq[bi * TILE + tid];
    else                   sqB[tid - TILE] = g_sq[bj * TILE + (tid - TILE)];

    const __nv_bfloat16* Ag = g_bf + (size_t)bi * TILE * D;
    const __nv_bfloat16* Bg = g_bf + (size_t)bj * TILE * D;

    // ---- cp.async chunk loader: 2048 x 16B per chunk, 8 per thread ----
    auto load_chunk = [&](int c) {
        const int stage = c & 1;
        #pragma unroll
        for (int v = 0; v < 8; v++) {
            int u   = v * 256 + tid;      // 0..2047
            int mat = u >> 10;            // 0=A, 1=B
            int r   = (u >> 3) & 127;
            int vi  = u & 7;
            const __nv_bfloat16* g =
                (mat ? Bg : Ag) + (size_t)r * D + c * CK + vi * 8;
            uint32_t dst = sb + stage * STAGEB + mat * MATB + r * ROWB + vi * 16;
            cp16(dst, g);
        }
    };

    // ---- ldmatrix addresses (relative; add stage offset + k offset later) ----
    uint32_t addrA[2];
    #pragma unroll
    for (int mt = 0; mt < 2; mt++) {
        int r = wm * 32 + mt * 16 + (lane & 15);
        int coff = (lane >> 4) * 8;
        addrA[mt] = sb + (uint32_t)(r * ROWB + coff * 2);
    }
    uint32_t addrB[4];
    #pragma unroll
    for (int nt4 = 0; nt4 < 4; nt4++) {
        int quad = lane >> 3;
        int r = wn * 64 + nt4 * 16 + (lane & 7) + ((quad & 2) ? 8 : 0);
        int coff = (quad & 1) * 8;
        addrB[nt4] = sb + MATB + (uint32_t)(r * ROWB + coff * 2);
    }

    float c[2][8][4];
    #pragma unroll
    for (int mt = 0; mt < 2; mt++)
        #pragma unroll
        for (int nt = 0; nt < 8; nt++)
            #pragma unroll
            for (int e = 0; e < 4; e++) c[mt][nt][e] = 0.f;

    // ---- prologue: prefetch chunks 0 and 1 ----
    load_chunk(0);
    asm volatile("cp.async.commit_group;" ::: "memory");
    load_chunk(1);
    asm volatile("cp.async.commit_group;" ::: "memory");

    // ---- pipelined mainloop over 4 K-chunks ----
    #pragma unroll
    for (int ch = 0; ch < NC; ch++) {
        asm volatile("cp.async.wait_group 1;" ::: "memory");
        __syncthreads();

        const uint32_t soff = (ch & 1) * STAGEB;
        #pragma unroll
        for (int kk = 0; kk < 4; kk++) {           // 4 x k16 per chunk
            uint32_t kb = soff + (uint32_t)kk * 32;
            uint32_t a[2][4];
            ldsm_x4(a[0][0], a[0][1], a[0][2], a[0][3], addrA[0] + kb);
            ldsm_x4(a[1][0], a[1][1], a[1][2], a[1][3], addrA[1] + kb);
            uint32_t b[4][4];
            #pragma unroll
            for (int nt4 = 0; nt4 < 4; nt4++)
                ldsm_x4(b[nt4][0], b[nt4][1], b[nt4][2], b[nt4][3],
                        addrB[nt4] + kb);
            #pragma unroll
            for (int mt = 0; mt < 2; mt++)
                #pragma unroll
                for (int nt4 = 0; nt4 < 4; nt4++) {
                    mma_bf16(c[mt][2 * nt4],     a[mt], b[nt4][0], b[nt4][1]);
                    mma_bf16(c[mt][2 * nt4 + 1], a[mt], b[nt4][2], b[nt4][3]);
                }
        }
        __syncthreads();                           // done reading this stage
        if (ch + 2 < NC) load_chunk(ch + 2);
        asm volatile("cp.async.commit_group;" ::: "memory");
    }

    // ---- epilogue ----
    const float NEG_L2E_16 = -1.4426950408889634f / 16.0f;
    const int g = lane >> 2;
    const int q = lane & 3;
    float wgt = (((bi < HALF_NT) == (bj < HALF_NT)) ? 1.0f : -1.0f)
              * ((bi == bj) ? 1.0f : 2.0f);

    float acc = 0.f;
    #pragma unroll
    for (int mt = 0; mt < 2; mt++) {
        #pragma unroll
        for (int nt = 0; nt < 8; nt++) {
            #pragma unroll
            for (int e = 0; e < 4; e++) {
                int r    = wm * 32 + mt * 16 + g + ((e >> 1) << 3);
                int cidx = wn * 64 + nt * 8 + q * 2 + (e & 1);
                float l2 = sqA[r] + sqB[cidx] - 2.0f * c[mt][nt][e];
                float u  = ex2f(l2 * NEG_L2E_16);   // exp(-l2/16)
                float u2 = u * u, u4 = u2 * u2, u8 = u4 * u4, u16 = u8 * u8;
                acc += ((u + u2) + (u4 + u8)) + u16;
            }
        }
    }
    #pragma unroll
    for (int o = 16; o; o >>= 1) acc += __shfl_xor_sync(0xFFFFFFFFu, acc, o);
    if (lane == 0) atomicAdd(&g_acc, (double)(acc * wgt));
}

// ---------------------------------------------------------------------------
// Kernel 3: finalize scalar
// ---------------------------------------------------------------------------
__global__ void fin_kernel(float* out) {
    out[0] = (float)(g_acc * (1.0 / ((double)N_SRC * (double)N_SRC)));
}

extern "C" void kernel_launch(void* const* d_in, const int* in_sizes, int n_in,
                              void* d_out, int out_size) {
    const float* src = (const float*)d_in[0];
    const float* tgt = (const float*)d_in[1];
    float* out = (float*)d_out;

    cudaFuncSetAttribute(mmd_kernel,
                         cudaFuncAttributeMaxDynamicSharedMemorySize, SMEM_TOTAL);

    prep_kernel<<<TOT / 8, 256>>>(src, tgt);
    dim3 grid(NT, NT);
    mmd_kernel<<<grid, 256, SMEM_TOTAL>>>();
    fin_kernel<<<1, 1>>>(out);
}